// round 14
// baseline (speedup 1.0000x reference)
#include <cuda_runtime.h>
#include <math.h>

#define BB 8
#define NN 2048
#define IND 128
#define OUTD 64
#define NEG_SLOPE 0.2f
#define TABS 136        // padded tab row: [0..64]=sufPos, [68..132]=prefNeg

// ---------------- scratch (static device globals; no allocations) ----------------
__device__ float g_hpT[BB * OUTD * NN];          // transposed [b][dim][row] (4 MB)
__device__ float g_s[BB * NN];
__device__ float g_d[BB * NN];
__device__ float g_sortedD[BB * NN];
__device__ float g_split[BB * 32];               // splitters: sd[64i+63] per batch
__device__ int   g_sortIdx[BB * NN];
__device__ float g_wp[BB * NN];                  // exp(d) at sorted position
__device__ float g_wq[BB * NN];                  // exp(0.2 d) at sorted position
__device__ float g_tab[(size_t)BB * 2049 * TABS];// (8.9 MB)
__device__ int   g_cnt[BB];                      // project-done counters (self-resetting)
__device__ int   g_sortdone[BB];
__device__ int   g_scanpass[BB];

__device__ __forceinline__ unsigned s2u(const void* p) {
    unsigned a;
    asm("{ .reg .u64 t; cvta.to.shared.u64 t, %1; cvt.u32.u64 %0, t; }"
        : "=r"(a) : "l"(p));
    return a;
}

// ==================== fused project + sort + scan ====================
// grid = 400 x 256 thr x 64KB dyn smem -> 3 blocks/SM -> ALL resident (no deadlock).
// blocks [0,256): project batch-major; [256,264): per-batch sort; [264,400): scans.
__global__ void __launch_bounds__(256) fusedK(
        const float* __restrict__ h, const float* __restrict__ W,
        const float* __restrict__ bfc,
        const float* __restrict__ asrc, const float* __restrict__ adst) {
    extern __shared__ float sm[];
    const int blk = blockIdx.x;
    const int t = threadIdx.x;

    if (blk < 256) {
        // ---------------- project: hp = h@W + b via packed f32x2 FMA ----------------
        float* sH = sm;                 // [64][128]  (32 KB)
        float* sW = sm + 64 * IND;      // [128][64]  (32 KB)
        const int rowBase = blk * 64;

        const float4* hsrc = (const float4*)(h + (size_t)rowBase * IND);
        float4* sH4 = (float4*)sH;
#pragma unroll
        for (int i = t; i < 64 * IND / 4; i += 256) sH4[i] = hsrc[i];
        const float4* wsrc = (const float4*)W;
        float4* sW4 = (float4*)sW;
#pragma unroll
        for (int i = t; i < IND * OUTD / 4; i += 256) sW4[i] = wsrc[i];
        __syncthreads();

        const int q = t & 15;
        const int g = t >> 4;
        const int c0 = q * 4;
        const int r0 = g * 4;

        const float4 b4 = *(const float4*)(bfc + c0);
        unsigned long long acc[4][2];
        {
            unsigned long long bp0, bp1;
            asm("mov.b64 %0, {%1, %2};" : "=l"(bp0) : "r"(__float_as_uint(b4.x)), "r"(__float_as_uint(b4.y)));
            asm("mov.b64 %0, {%1, %2};" : "=l"(bp1) : "r"(__float_as_uint(b4.z)), "r"(__float_as_uint(b4.w)));
#pragma unroll
            for (int r = 0; r < 4; r++) { acc[r][0] = bp0; acc[r][1] = bp1; }
        }

        const unsigned swu = s2u(sW) + c0 * 4u;

        for (int k = 0; k < IND; k += 4) {
            float hv[4][4];
#pragma unroll
            for (int r = 0; r < 4; r++) {
                const float4 a = *(const float4*)&sH[(r0 + r) * IND + k];
                hv[r][0] = a.x; hv[r][1] = a.y; hv[r][2] = a.z; hv[r][3] = a.w;
            }
            unsigned long long wv[4][2];
#pragma unroll
            for (int kk = 0; kk < 4; kk++) {
                asm volatile("ld.shared.v2.b64 {%0, %1}, [%2];"
                             : "=l"(wv[kk][0]), "=l"(wv[kk][1])
                             : "r"(swu + (unsigned)((k + kk) * OUTD * 4)));
            }
#pragma unroll
            for (int kk = 0; kk < 4; kk++) {
#pragma unroll
                for (int r = 0; r < 4; r++) {
                    unsigned long long hh;
                    const unsigned hb = __float_as_uint(hv[r][kk]);
                    asm("mov.b64 %0, {%1, %1};" : "=l"(hh) : "r"(hb));
                    asm("fma.rn.f32x2 %0, %1, %2, %3;"
                        : "=l"(acc[r][0]) : "l"(hh), "l"(wv[kk][0]), "l"(acc[r][0]));
                    asm("fma.rn.f32x2 %0, %1, %2, %3;"
                        : "=l"(acc[r][1]) : "l"(hh), "l"(wv[kk][1]), "l"(acc[r][1]));
                }
            }
        }

        float av[4][4];
#pragma unroll
        for (int r = 0; r < 4; r++)
#pragma unroll
            for (int p = 0; p < 2; p++) {
                unsigned lo, hi;
                asm("mov.b64 {%0, %1}, %2;" : "=r"(lo), "=r"(hi) : "l"(acc[r][p]));
                av[r][2 * p] = __uint_as_float(lo);
                av[r][2 * p + 1] = __uint_as_float(hi);
            }

        // s/d epilogue
        const float4 as4 = *(const float4*)(asrc + c0);
        const float4 ad4 = *(const float4*)(adst + c0);
        float sp[4], dp[4];
#pragma unroll
        for (int r = 0; r < 4; r++) {
            sp[r] = fmaf(av[r][0], as4.x, fmaf(av[r][1], as4.y,
                     fmaf(av[r][2], as4.z, av[r][3] * as4.w)));
            dp[r] = fmaf(av[r][0], ad4.x, fmaf(av[r][1], ad4.y,
                     fmaf(av[r][2], ad4.z, av[r][3] * ad4.w)));
        }
#pragma unroll
        for (int o = 1; o < 16; o <<= 1)
#pragma unroll
            for (int r = 0; r < 4; r++) {
                sp[r] += __shfl_xor_sync(0xffffffffu, sp[r], o);
                dp[r] += __shfl_xor_sync(0xffffffffu, dp[r], o);
            }
        if (q == 0)
#pragma unroll
            for (int r = 0; r < 4; r++) {
                g_s[rowBase + r0 + r] = sp[r];
                g_d[rowBase + r0 + r] = dp[r];
            }

        // transpose epilogue -> g_hpT
        __syncthreads();
        float* tile = sm;                   // [64][65]
#pragma unroll
        for (int r = 0; r < 4; r++)
#pragma unroll
            for (int c = 0; c < 4; c++)
                tile[(c0 + c) * 65 + (r0 + r)] = av[r][c];
        __syncthreads();

        const int b = rowBase >> 11;
        const int rib = rowBase & (NN - 1);
        for (int f = t; f < 64 * 64; f += 256) {
            const int dim = f >> 6, i = f & 63;
            g_hpT[((size_t)(b * OUTD + dim)) * NN + rib + i] = tile[dim * 65 + i];
        }

        // signal: this project block done
        __threadfence();
        __syncthreads();
        if (t == 0) atomicAdd(&g_cnt[b], 1);

    } else if (blk < 264) {
        // ---------------- sort batch b (256 threads, 4 CE per thread per stage) ------
        const int b = blk - 256;
        if (t == 0) {
            while (atomicAdd(&g_cnt[b], 0) < 32) { }
            __threadfence();
        }
        __syncthreads();

        unsigned long long* su = (unsigned long long*)sm;   // 16 KB of the 64 KB
        for (int i = t; i < NN; i += 256) {
            const unsigned bits = __float_as_uint(g_d[b * NN + i]);
            const unsigned key = bits ^ ((bits & 0x80000000u) ? 0xFFFFFFFFu : 0x80000000u);
            su[i] = ((unsigned long long)key << 32) | (unsigned)i;
        }
        __syncthreads();

        for (int k = 2; k <= NN; k <<= 1) {
            for (int j = k >> 1; j > 0; j >>= 1) {
#pragma unroll
                for (int v = 0; v < 4; v++) {
                    const int tt = t + 256 * v;
                    const int i = ((tt & ~(j - 1)) << 1) | (tt & (j - 1));
                    const int partner = i | j;
                    const bool up = ((i & k) == 0);
                    const unsigned long long A = su[i], B = su[partner];
                    const unsigned long long lo_ = (A < B) ? A : B;
                    const unsigned long long hi_ = (A < B) ? B : A;
                    su[i] = up ? lo_ : hi_;
                    su[partner] = up ? hi_ : lo_;
                }
                __syncthreads();
            }
        }

        for (int i = t; i < NN; i += 256) {
            const unsigned long long u = su[i];
            const unsigned key = (unsigned)(u >> 32);
            const unsigned bits = key ^ ((key & 0x80000000u) ? 0x80000000u : 0xFFFFFFFFu);
            const float dv = __uint_as_float(bits);
            g_sortedD[b * NN + i] = dv;
            g_sortIdx[b * NN + i] = (int)(u & 0xFFFFFFFFu);
            g_wp[b * NN + i] = __expf(dv);
            g_wq[b * NN + i] = __expf(NEG_SLOPE * dv);
            if ((i & 63) == 63) g_split[b * 32 + (i >> 6)] = dv;
        }

        __threadfence();
        __syncthreads();
        if (t == 0) atomicExch(&g_sortdone[b], 1);

    } else {
        // ---------------- scan: block = (b, g); g<16 -> dims 4g..4g+3, g==16 -> weights
        const int r2 = blk - 264;
        const int b = r2 / 17;
        const int g = r2 - b * 17;
        if (t == 0) {
            while (atomicAdd(&g_sortdone[b], 0) == 0) { }
            // reset flags for next graph replay once ALL 17 scan blocks have passed
            const int p = atomicAdd(&g_scanpass[b], 1);
            if (p == 16) {
                atomicExch(&g_cnt[b], 0);
                atomicExch(&g_sortdone[b], 0);
                atomicExch(&g_scanpass[b], 0);
            }
            __threadfence();
        }
        __syncthreads();

        const int lane = t & 31, warp = t >> 5;
        const int base = b * NN;
        float* tabb = g_tab + (size_t)b * 2049 * TABS;

        if (g < 16) {
            const int d0 = g * 4;
            const float* __restrict__ hp0 = g_hpT + ((size_t)(b * OUTD + d0)) * NN;

            float vp[4][8], vn[4][8];
#pragma unroll
            for (int e = 0; e < 8; e++) {
                const int r = t * 8 + e;
                const float wpv = g_wp[base + r];
                const float wqv = g_wq[base + r];
                const int j = g_sortIdx[base + r];
#pragma unroll
                for (int d = 0; d < 4; d++) {
                    const float val = hp0[(size_t)d * NN + j];
                    vp[d][e] = wpv * val;
                    vn[d][e] = wqv * val;
                }
            }

#pragma unroll
            for (int d = 0; d < 4; d++) {
#pragma unroll
                for (int e = 1; e < 8; e++) vn[d][e] += vn[d][e - 1];
#pragma unroll
                for (int e = 6; e >= 0; e--) vp[d][e] += vp[d][e + 1];
            }

            __shared__ float wtn[4][8], wtp[4][8];
            float xn[4], xp[4], totn[4], totp[4];
#pragma unroll
            for (int d = 0; d < 4; d++) { totn[d] = vn[d][7]; totp[d] = vp[d][0];
                                          xn[d] = totn[d];    xp[d] = totp[d]; }
#pragma unroll
            for (int o = 1; o < 32; o <<= 1)
#pragma unroll
                for (int d = 0; d < 4; d++) {
                    const float yn = __shfl_up_sync(0xffffffffu, xn[d], o);
                    if (lane >= o) xn[d] += yn;
                    const float yp = __shfl_down_sync(0xffffffffu, xp[d], o);
                    if (lane < 32 - o) xp[d] += yp;
                }
            if (lane == 31) { wtn[0][warp] = xn[0]; wtn[1][warp] = xn[1];
                              wtn[2][warp] = xn[2]; wtn[3][warp] = xn[3]; }
            if (lane == 0)  { wtp[0][warp] = xp[0]; wtp[1][warp] = xp[1];
                              wtp[2][warp] = xp[2]; wtp[3][warp] = xp[3]; }
            __syncthreads();

            float basen[4], basep[4];
#pragma unroll
            for (int d = 0; d < 4; d++) {
                float offn = 0.f, offp = 0.f;
#pragma unroll
                for (int w2 = 0; w2 < 8; w2++) {
                    if (w2 < warp) offn += wtn[d][w2];
                    if (w2 > warp) offp += wtp[d][w2];
                }
                basen[d] = offn + xn[d] - totn[d];
                basep[d] = offp + xp[d] - totp[d];
            }

#pragma unroll
            for (int e = 0; e < 8; e++) {
                const int kp = t * 8 + e;
                float4 s4; s4.x = basep[0] + vp[0][e]; s4.y = basep[1] + vp[1][e];
                           s4.z = basep[2] + vp[2][e]; s4.w = basep[3] + vp[3][e];
                *(float4*)&tabb[(size_t)kp * TABS + d0] = s4;
                float4 n4; n4.x = basen[0] + vn[0][e]; n4.y = basen[1] + vn[1][e];
                           n4.z = basen[2] + vn[2][e]; n4.w = basen[3] + vn[3][e];
                *(float4*)&tabb[(size_t)(kp + 1) * TABS + 68 + d0] = n4;
            }
            if (t == 0) {
                const float4 z = {0.f, 0.f, 0.f, 0.f};
                *(float4*)&tabb[(size_t)2048 * TABS + d0] = z;
                *(float4*)&tabb[68 + d0] = z;
            }
        } else {
            float vp[8], vn[8];
#pragma unroll
            for (int e = 0; e < 8; e++) {
                const int r = t * 8 + e;
                vp[e] = g_wp[base + r];
                vn[e] = g_wq[base + r];
            }
#pragma unroll
            for (int e = 1; e < 8; e++) vn[e] += vn[e - 1];
#pragma unroll
            for (int e = 6; e >= 0; e--) vp[e] += vp[e + 1];
            const float totn = vn[7], totp = vp[0];

            __shared__ float wtn1[8], wtp1[8];
            float xn = totn, xp = totp;
#pragma unroll
            for (int o = 1; o < 32; o <<= 1) {
                const float yn = __shfl_up_sync(0xffffffffu, xn, o);
                if (lane >= o) xn += yn;
                const float yp = __shfl_down_sync(0xffffffffu, xp, o);
                if (lane < 32 - o) xp += yp;
            }
            if (lane == 31) wtn1[warp] = xn;
            if (lane == 0)  wtp1[warp] = xp;
            __syncthreads();

            float offn = 0.f, offp = 0.f;
#pragma unroll
            for (int w2 = 0; w2 < 8; w2++) {
                if (w2 < warp) offn += wtn1[w2];
                if (w2 > warp) offp += wtp1[w2];
            }
            const float basen = offn + xn - totn;
            const float basep = offp + xp - totp;

#pragma unroll
            for (int e = 0; e < 8; e++) {
                const int kp = t * 8 + e;
                tabb[(size_t)kp * TABS + 64] = basep + vp[e];
                tabb[(size_t)(kp + 1) * TABS + 68 + 64] = basen + vn[e];
            }
            if (t == 0) {
                tabb[(size_t)2048 * TABS + 64] = 0.f;
                tabb[68 + 64] = 0.f;
            }
        }
    }
}

// ---------------- kernel 2: per-row output — 2 rows/warp, float2 tab access ----------
__global__ void outK(const float* __restrict__ battn, float* __restrict__ out) {
    const int warp = threadIdx.x >> 5, lane = threadIdx.x & 31;
    const int row0 = blockIdx.x * 16 + warp * 2;   // rows row0, row0+1 (same batch)
    const int b = row0 >> 11;                      // NN = 2048

    const float ba = *battn;
    const float si0 = g_s[row0] + ba;
    const float si1 = g_s[row0 + 1] + ba;
    const float tt0 = -si0, tt1 = -si1;
    const float* __restrict__ sd = g_sortedD + b * NN;

    const float spv = g_split[b * 32 + lane];
    const unsigned ba0 = __ballot_sync(0xffffffffu, spv < tt0);
    const unsigned ba1 = __ballot_sync(0xffffffffu, spv < tt1);
    const int c10 = __popc(ba0), c11 = __popc(ba1);
    const int w00 = (c10 < 32 ? c10 : 31) * 64;
    const int w01 = (c11 < 32 ? c11 : 31) * 64;

    const float p0 = sd[w00 + lane * 2 + 1];
    const float p1 = sd[w01 + lane * 2 + 1];
    const unsigned bb0 = __ballot_sync(0xffffffffu, p0 < tt0);
    const unsigned bb1 = __ballot_sync(0xffffffffu, p1 < tt1);
    int c20 = __popc(bb0); c20 = c20 < 31 ? c20 : 31;
    int c21 = __popc(bb1); c21 = c21 < 31 ? c21 : 31;

    const float q0 = sd[w00 + 2 * c20];
    const float q1 = sd[w01 + 2 * c21];
    int lo0 = w00 + 2 * c20 + (q0 < tt0 ? 1 : 0);
    int lo1 = w01 + 2 * c21 + (q1 < tt1 ? 1 : 0);
    if (c10 == 32) lo0 = NN;
    if (c11 == 32) lo1 = NN;

    const float P0 = __expf(si0), Q0 = __expf(NEG_SLOPE * si0);
    const float P1 = __expf(si1), Q1 = __expf(NEG_SLOPE * si1);
    const float* __restrict__ tb0 = g_tab + ((size_t)b * 2049 + lo0) * TABS;
    const float* __restrict__ tb1 = g_tab + ((size_t)b * 2049 + lo1) * TABS;

    const float2 s0 = *(const float2*)&tb0[2 * lane];
    const float2 n0 = *(const float2*)&tb0[68 + 2 * lane];
    const float2 s1 = *(const float2*)&tb1[2 * lane];
    const float2 n1 = *(const float2*)&tb1[68 + 2 * lane];
    const float den0 = fmaf(P0, tb0[64], Q0 * tb0[132]);
    const float den1 = fmaf(P1, tb1[64], Q1 * tb1[132]);
    const float inv0 = 1.0f / den0;
    const float inv1 = 1.0f / den1;

    float2 o0, o1;
    o0.x = fmaf(P0, s0.x, Q0 * n0.x) * inv0;
    o0.y = fmaf(P0, s0.y, Q0 * n0.y) * inv0;
    o1.x = fmaf(P1, s1.x, Q1 * n1.x) * inv1;
    o1.y = fmaf(P1, s1.y, Q1 * n1.y) * inv1;
    o0.x = (o0.x > 0.f) ? o0.x : (__expf(o0.x) - 1.0f);   // ELU (alpha=1)
    o0.y = (o0.y > 0.f) ? o0.y : (__expf(o0.y) - 1.0f);
    o1.x = (o1.x > 0.f) ? o1.x : (__expf(o1.x) - 1.0f);
    o1.y = (o1.y > 0.f) ? o1.y : (__expf(o1.y) - 1.0f);

    *(float2*)&out[(size_t)row0 * OUTD + 2 * lane] = o0;
    *(float2*)&out[(size_t)(row0 + 1) * OUTD + 2 * lane] = o1;
}

// ---------------- launch: 2 nodes ----------------
extern "C" void kernel_launch(void* const* d_in, const int* in_sizes, int n_in,
                              void* d_out, int out_size) {
    const float* h     = (const float*)d_in[0];
    const float* W     = (const float*)d_in[1];
    const float* bfc   = (const float*)d_in[2];
    const float* asrc  = (const float*)d_in[3];
    const float* adst  = (const float*)d_in[4];
    const float* battn = (const float*)d_in[5];
    float* out = (float*)d_out;

    cudaFuncSetAttribute(fusedK, cudaFuncAttributeMaxDynamicSharedMemorySize, 64 * 1024);

    fusedK<<<256 + BB + BB * 17, 256, 64 * 1024>>>(h, W, bfc, asrc, adst);
    outK<<<(BB * NN) / 16, 256>>>(battn, out);
}

// round 15
// speedup vs baseline: 1.6436x; 1.6436x over previous
#include <cuda_runtime.h>
#include <math.h>

#define BB 8
#define NN 2048
#define IND 128
#define OUTD 64
#define NEG_SLOPE 0.2f
#define TABS 136        // padded tab row: [0..64]=sufPos, [68..132]=prefNeg

// ---------------- scratch (static device globals; no allocations) ----------------
__device__ float g_hpT[BB * OUTD * NN];          // transposed [b][dim][row] (4 MB)
__device__ float g_s[BB * NN];
__device__ float g_d[BB * NN];
__device__ float g_sortedD[BB * NN];
__device__ float g_split[BB * 32];               // splitters: sd[64i+63] per batch
__device__ int   g_sortIdx[BB * NN];
__device__ float g_wp[BB * NN];                  // exp(d) at sorted position
__device__ float g_wq[BB * NN];                  // exp(0.2 d) at sorted position
__device__ float g_tab[(size_t)BB * 2049 * TABS];// (8.9 MB)

__device__ __forceinline__ unsigned s2u(const void* p) {
    unsigned a;
    asm("{ .reg .u64 t; cvta.to.shared.u64 t, %1; cvt.u32.u64 %0, t; }"
        : "=r"(a) : "l"(p));
    return a;
}

// ---------------- kernel 1: hp = h @ W_fc + b_fc via packed f32x2 FMA ----------
__global__ void projectK(const float* __restrict__ h, const float* __restrict__ W,
                         const float* __restrict__ bfc,
                         const float* __restrict__ asrc, const float* __restrict__ adst) {
    extern __shared__ float sm[];
    float* sH = sm;                 // [64][128]  (32 KB)
    float* sW = sm + 64 * IND;      // [128][64]  (32 KB)
    const int t = threadIdx.x;
    const int rowBase = blockIdx.x * 64;

    const float4* hsrc = (const float4*)(h + (size_t)rowBase * IND);
    float4* sH4 = (float4*)sH;
#pragma unroll
    for (int i = t; i < 64 * IND / 4; i += 256) sH4[i] = hsrc[i];
    const float4* wsrc = (const float4*)W;
    float4* sW4 = (float4*)sW;
#pragma unroll
    for (int i = t; i < IND * OUTD / 4; i += 256) sW4[i] = wsrc[i];
    __syncthreads();

    const int q = t & 15;     // col quad: cols 4q..4q+3
    const int g = t >> 4;     // row group: rows 4g..4g+3
    const int c0 = q * 4;
    const int r0 = g * 4;

    // packed accumulators: acc[r][p] holds cols (c0+2p, c0+2p+1) for row r0+r
    const float4 b4 = *(const float4*)(bfc + c0);
    unsigned long long acc[4][2];
    {
        unsigned long long bp0, bp1;
        asm("mov.b64 %0, {%1, %2};" : "=l"(bp0) : "r"(__float_as_uint(b4.x)), "r"(__float_as_uint(b4.y)));
        asm("mov.b64 %0, {%1, %2};" : "=l"(bp1) : "r"(__float_as_uint(b4.z)), "r"(__float_as_uint(b4.w)));
#pragma unroll
        for (int r = 0; r < 4; r++) { acc[r][0] = bp0; acc[r][1] = bp1; }
    }

    const unsigned swu = s2u(sW) + c0 * 4u;

    for (int k = 0; k < IND; k += 4) {
        float hv[4][4];
#pragma unroll
        for (int r = 0; r < 4; r++) {
            const float4 a = *(const float4*)&sH[(r0 + r) * IND + k];
            hv[r][0] = a.x; hv[r][1] = a.y; hv[r][2] = a.z; hv[r][3] = a.w;
        }
        unsigned long long wv[4][2];
#pragma unroll
        for (int kk = 0; kk < 4; kk++) {
            asm volatile("ld.shared.v2.b64 {%0, %1}, [%2];"
                         : "=l"(wv[kk][0]), "=l"(wv[kk][1])
                         : "r"(swu + (unsigned)((k + kk) * OUTD * 4)));
        }
#pragma unroll
        for (int kk = 0; kk < 4; kk++) {
#pragma unroll
            for (int r = 0; r < 4; r++) {
                unsigned long long hh;
                const unsigned hb = __float_as_uint(hv[r][kk]);
                asm("mov.b64 %0, {%1, %1};" : "=l"(hh) : "r"(hb));
                asm("fma.rn.f32x2 %0, %1, %2, %3;"
                    : "=l"(acc[r][0]) : "l"(hh), "l"(wv[kk][0]), "l"(acc[r][0]));
                asm("fma.rn.f32x2 %0, %1, %2, %3;"
                    : "=l"(acc[r][1]) : "l"(hh), "l"(wv[kk][1]), "l"(acc[r][1]));
            }
        }
    }

    // unpack accumulators once
    float av[4][4];
#pragma unroll
    for (int r = 0; r < 4; r++) {
#pragma unroll
        for (int p = 0; p < 2; p++) {
            unsigned lo, hi;
            asm("mov.b64 {%0, %1}, %2;" : "=r"(lo), "=r"(hi) : "l"(acc[r][p]));
            av[r][2 * p] = __uint_as_float(lo);
            av[r][2 * p + 1] = __uint_as_float(hi);
        }
    }

    // ---- fused s/d epilogue: 16-lane shuffle reduce across col-quads ----
    const float4 as4 = *(const float4*)(asrc + c0);
    const float4 ad4 = *(const float4*)(adst + c0);
    float sp[4], dp[4];
#pragma unroll
    for (int r = 0; r < 4; r++) {
        sp[r] = fmaf(av[r][0], as4.x, fmaf(av[r][1], as4.y,
                 fmaf(av[r][2], as4.z, av[r][3] * as4.w)));
        dp[r] = fmaf(av[r][0], ad4.x, fmaf(av[r][1], ad4.y,
                 fmaf(av[r][2], ad4.z, av[r][3] * ad4.w)));
    }
#pragma unroll
    for (int o = 1; o < 16; o <<= 1) {
#pragma unroll
        for (int r = 0; r < 4; r++) {
            sp[r] += __shfl_xor_sync(0xffffffffu, sp[r], o);
            dp[r] += __shfl_xor_sync(0xffffffffu, dp[r], o);
        }
    }
    if (q == 0) {
#pragma unroll
        for (int r = 0; r < 4; r++) {
            g_s[rowBase + r0 + r] = sp[r];
            g_d[rowBase + r0 + r] = dp[r];
        }
    }

    // ---- transpose epilogue: emit g_hpT[b][dim][row] ----
    __syncthreads();                    // done reading sH
    float* tile = sm;                   // [64 dims][65 pad]
#pragma unroll
    for (int r = 0; r < 4; r++)
#pragma unroll
        for (int c = 0; c < 4; c++)
            tile[(c0 + c) * 65 + (r0 + r)] = av[r][c];
    __syncthreads();

    const int b = rowBase >> 11;
    const int rib = rowBase & (NN - 1);
    for (int f = t; f < 64 * 64; f += 256) {
        const int dim = f >> 6, i = f & 63;
        g_hpT[((size_t)(b * OUTD + dim)) * NN + rib + i] = tile[dim * 65 + i];
    }
}

// ---------------- kernel 2: per-batch bitonic sort, 32-bit packed keys ----------------
// key = (sortable_u & 0xFFFFF800) | idx  (21 order bits + 11-bit index).
// Order is monotone in d up to truncation ties (error ~1e-5 in weights, <<1e-3 budget).
// Epilogue recovers EXACT d via g_d[idx].
__global__ void sortK() {
    const int b = blockIdx.x;
    __shared__ unsigned su[NN];       // 8 KB (was 16 KB) -> half the crossbar traffic
    const int t = threadIdx.x;  // 1024

    for (int i = t; i < NN; i += 1024) {
        const unsigned bits = __float_as_uint(g_d[b * NN + i]);
        const unsigned key = bits ^ ((bits & 0x80000000u) ? 0xFFFFFFFFu : 0x80000000u);
        su[i] = (key & 0xFFFFF800u) | (unsigned)i;
    }
    __syncthreads();

    for (int k = 2; k <= NN; k <<= 1) {
        for (int j = k >> 1; j > 0; j >>= 1) {
            const int i = ((t & ~(j - 1)) << 1) | (t & (j - 1));
            const int partner = i | j;
            const bool up = ((i & k) == 0);
            const unsigned A = su[i], B = su[partner];
            const unsigned lo_ = (A < B) ? A : B;
            const unsigned hi_ = (A < B) ? B : A;
            su[i] = up ? lo_ : hi_;
            su[partner] = up ? hi_ : lo_;
            if (j >= 64) __syncthreads(); else __syncwarp();
        }
        __syncthreads();
    }

    for (int i = t; i < NN; i += 1024) {
        const unsigned u = su[i];
        const int idx = (int)(u & 0x7FFu);
        const float dv = g_d[b * NN + idx];     // exact value via index
        g_sortedD[b * NN + i] = dv;
        g_sortIdx[b * NN + i] = idx;
        g_wp[b * NN + i] = __expf(dv);
        g_wq[b * NN + i] = __expf(NEG_SLOPE * dv);
        if ((i & 63) == 63) g_split[b * 32 + (i >> 6)] = dv;   // splitter table
    }
}

// ---------------- kernel 3: fused dual scan, 4 dims per block, float4 tab stores ----
// blockIdx.x = b*17 + g. g<16: dims 4g..4g+3. g==16: weight series (val=1).
__global__ void scanK() {
    const int blk = blockIdx.x;
    const int b = blk / 17;
    const int g = blk - b * 17;
    const int t = threadIdx.x;           // 256, each owns 8 consecutive positions
    const int lane = t & 31, warp = t >> 5;
    const int base = b * NN;
    float* tabb = g_tab + (size_t)b * 2049 * TABS;

    if (g < 16) {
        const int d0 = g * 4;
        const float* __restrict__ hp0 = g_hpT + ((size_t)(b * OUTD + d0)) * NN;

        float vp[4][8], vn[4][8];
#pragma unroll
        for (int e = 0; e < 8; e++) {
            const int r = t * 8 + e;
            const float wpv = g_wp[base + r];
            const float wqv = g_wq[base + r];
            const int j = g_sortIdx[base + r];
#pragma unroll
            for (int d = 0; d < 4; d++) {
                const float val = hp0[(size_t)d * NN + j];   // 4x 8KB L1-resident rows
                vp[d][e] = wpv * val;
                vn[d][e] = wqv * val;
            }
        }

        // intra-chunk scans: neg forward, pos backward
#pragma unroll
        for (int d = 0; d < 4; d++) {
#pragma unroll
            for (int e = 1; e < 8; e++) vn[d][e] += vn[d][e - 1];
#pragma unroll
            for (int e = 6; e >= 0; e--) vp[d][e] += vp[d][e + 1];
        }

        __shared__ float wtn[4][8], wtp[4][8];
        float xn[4], xp[4], totn[4], totp[4];
#pragma unroll
        for (int d = 0; d < 4; d++) { totn[d] = vn[d][7]; totp[d] = vp[d][0];
                                      xn[d] = totn[d];    xp[d] = totp[d]; }
#pragma unroll
        for (int o = 1; o < 32; o <<= 1) {
#pragma unroll
            for (int d = 0; d < 4; d++) {
                const float yn = __shfl_up_sync(0xffffffffu, xn[d], o);
                if (lane >= o) xn[d] += yn;
                const float yp = __shfl_down_sync(0xffffffffu, xp[d], o);
                if (lane < 32 - o) xp[d] += yp;
            }
        }
        if (lane == 31) { wtn[0][warp] = xn[0]; wtn[1][warp] = xn[1];
                          wtn[2][warp] = xn[2]; wtn[3][warp] = xn[3]; }
        if (lane == 0)  { wtp[0][warp] = xp[0]; wtp[1][warp] = xp[1];
                          wtp[2][warp] = xp[2]; wtp[3][warp] = xp[3]; }
        __syncthreads();

        float basen[4], basep[4];
#pragma unroll
        for (int d = 0; d < 4; d++) {
            float offn = 0.f, offp = 0.f;
#pragma unroll
            for (int w2 = 0; w2 < 8; w2++) {
                if (w2 < warp) offn += wtn[d][w2];
                if (w2 > warp) offp += wtp[d][w2];
            }
            basen[d] = offn + xn[d] - totn[d];
            basep[d] = offp + xp[d] - totp[d];
        }

#pragma unroll
        for (int e = 0; e < 8; e++) {
            const int kp = t * 8 + e;
            float4 s4; s4.x = basep[0] + vp[0][e]; s4.y = basep[1] + vp[1][e];
                       s4.z = basep[2] + vp[2][e]; s4.w = basep[3] + vp[3][e];
            *(float4*)&tabb[(size_t)kp * TABS + d0] = s4;                 // sufPos[k]
            float4 n4; n4.x = basen[0] + vn[0][e]; n4.y = basen[1] + vn[1][e];
                       n4.z = basen[2] + vn[2][e]; n4.w = basen[3] + vn[3][e];
            *(float4*)&tabb[(size_t)(kp + 1) * TABS + 68 + d0] = n4;      // prefNeg[k+1]
        }
        if (t == 0) {
            const float4 z = {0.f, 0.f, 0.f, 0.f};
            *(float4*)&tabb[(size_t)2048 * TABS + d0] = z;    // sufPos[2048]
            *(float4*)&tabb[68 + d0] = z;                      // prefNeg[0]
        }
    } else {
        // weight series: val = 1 -> scan wp (suffix) and wq (prefix) directly
        float vp[8], vn[8];
#pragma unroll
        for (int e = 0; e < 8; e++) {
            const int r = t * 8 + e;
            vp[e] = g_wp[base + r];
            vn[e] = g_wq[base + r];
        }
#pragma unroll
        for (int e = 1; e < 8; e++) vn[e] += vn[e - 1];
#pragma unroll
        for (int e = 6; e >= 0; e--) vp[e] += vp[e + 1];
        const float totn = vn[7], totp = vp[0];

        __shared__ float wtn1[8], wtp1[8];
        float xn = totn, xp = totp;
#pragma unroll
        for (int o = 1; o < 32; o <<= 1) {
            const float yn = __shfl_up_sync(0xffffffffu, xn, o);
            if (lane >= o) xn += yn;
            const float yp = __shfl_down_sync(0xffffffffu, xp, o);
            if (lane < 32 - o) xp += yp;
        }
        if (lane == 31) wtn1[warp] = xn;
        if (lane == 0)  wtp1[warp] = xp;
        __syncthreads();

        float offn = 0.f, offp = 0.f;
#pragma unroll
        for (int w2 = 0; w2 < 8; w2++) {
            if (w2 < warp) offn += wtn1[w2];
            if (w2 > warp) offp += wtp1[w2];
        }
        const float basen = offn + xn - totn;
        const float basep = offp + xp - totp;

#pragma unroll
        for (int e = 0; e < 8; e++) {
            const int kp = t * 8 + e;
            tabb[(size_t)kp * TABS + 64] = basep + vp[e];               // sufPos weight
            tabb[(size_t)(kp + 1) * TABS + 68 + 64] = basen + vn[e];    // prefNeg weight
        }
        if (t == 0) {
            tabb[(size_t)2048 * TABS + 64] = 0.f;
            tabb[68 + 64] = 0.f;
        }
    }
}

// ---------------- kernel 4: per-row output — 2 rows/warp, float2 tab access ----------
__global__ void outK(const float* __restrict__ battn, float* __restrict__ out) {
    const int warp = threadIdx.x >> 5, lane = threadIdx.x & 31;
    const int row0 = blockIdx.x * 16 + warp * 2;   // rows row0, row0+1 (same batch)
    const int b = row0 >> 11;                      // NN = 2048

    const float ba = *battn;
    const float si0 = g_s[row0] + ba;
    const float si1 = g_s[row0 + 1] + ba;
    const float tt0 = -si0, tt1 = -si1;
    const float* __restrict__ sd = g_sortedD + b * NN;

    // round 1: one splitter line serves both rows
    const float spv = g_split[b * 32 + lane];
    const unsigned ba0 = __ballot_sync(0xffffffffu, spv < tt0);
    const unsigned ba1 = __ballot_sync(0xffffffffu, spv < tt1);
    const int c10 = __popc(ba0), c11 = __popc(ba1);
    const int w00 = (c10 < 32 ? c10 : 31) * 64;
    const int w01 = (c11 < 32 ? c11 : 31) * 64;

    // round 2: both probes issued back-to-back (MLP=2)
    const float p0 = sd[w00 + lane * 2 + 1];
    const float p1 = sd[w01 + lane * 2 + 1];
    const unsigned bb0 = __ballot_sync(0xffffffffu, p0 < tt0);
    const unsigned bb1 = __ballot_sync(0xffffffffu, p1 < tt1);
    int c20 = __popc(bb0); c20 = c20 < 31 ? c20 : 31;
    int c21 = __popc(bb1); c21 = c21 < 31 ? c21 : 31;

    // round 3
    const float q0 = sd[w00 + 2 * c20];
    const float q1 = sd[w01 + 2 * c21];
    int lo0 = w00 + 2 * c20 + (q0 < tt0 ? 1 : 0);
    int lo1 = w01 + 2 * c21 + (q1 < tt1 ? 1 : 0);
    if (c10 == 32) lo0 = NN;
    if (c11 == 32) lo1 = NN;

    const float P0 = __expf(si0), Q0 = __expf(NEG_SLOPE * si0);
    const float P1 = __expf(si1), Q1 = __expf(NEG_SLOPE * si1);
    const float* __restrict__ tb0 = g_tab + ((size_t)b * 2049 + lo0) * TABS;
    const float* __restrict__ tb1 = g_tab + ((size_t)b * 2049 + lo1) * TABS;

    const float2 s0 = *(const float2*)&tb0[2 * lane];
    const float2 n0 = *(const float2*)&tb0[68 + 2 * lane];
    const float2 s1 = *(const float2*)&tb1[2 * lane];
    const float2 n1 = *(const float2*)&tb1[68 + 2 * lane];
    const float den0 = fmaf(P0, tb0[64], Q0 * tb0[132]);
    const float den1 = fmaf(P1, tb1[64], Q1 * tb1[132]);
    const float inv0 = 1.0f / den0;
    const float inv1 = 1.0f / den1;

    float2 o0, o1;
    o0.x = fmaf(P0, s0.x, Q0 * n0.x) * inv0;
    o0.y = fmaf(P0, s0.y, Q0 * n0.y) * inv0;
    o1.x = fmaf(P1, s1.x, Q1 * n1.x) * inv1;
    o1.y = fmaf(P1, s1.y, Q1 * n1.y) * inv1;
    o0.x = (o0.x > 0.f) ? o0.x : (__expf(o0.x) - 1.0f);   // ELU (alpha=1)
    o0.y = (o0.y > 0.f) ? o0.y : (__expf(o0.y) - 1.0f);
    o1.x = (o1.x > 0.f) ? o1.x : (__expf(o1.x) - 1.0f);
    o1.y = (o1.y > 0.f) ? o1.y : (__expf(o1.y) - 1.0f);

    *(float2*)&out[(size_t)row0 * OUTD + 2 * lane] = o0;
    *(float2*)&out[(size_t)(row0 + 1) * OUTD + 2 * lane] = o1;
}

// ---------------- launch: single stream ----------------
extern "C" void kernel_launch(void* const* d_in, const int* in_sizes, int n_in,
                              void* d_out, int out_size) {
    const float* h     = (const float*)d_in[0];
    const float* W     = (const float*)d_in[1];
    const float* bfc   = (const float*)d_in[2];
    const float* asrc  = (const float*)d_in[3];
    const float* adst  = (const float*)d_in[4];
    const float* battn = (const float*)d_in[5];
    float* out = (float*)d_out;

    cudaFuncSetAttribute(projectK, cudaFuncAttributeMaxDynamicSharedMemorySize, 64 * 1024);

    projectK<<<(BB * NN) / 64, 256, 64 * 1024>>>(h, W, bfc, asrc, adst);
    sortK<<<BB, 1024>>>();
    scanK<<<BB * 17, 256>>>();
    outK<<<(BB * NN) / 16, 256>>>(battn, out);
}